// round 1
// baseline (speedup 1.0000x reference)
#include <cuda_runtime.h>

// ---------------- problem constants ----------------
#define B_        8
#define S_        1024
#define D_        4096
#define DV_       1024
#define IMG_      336
#define PATCH_    14
#define GRID_     24          // IMG/PATCH
#define NP_       576         // GRID*GRID
#define MAXE_     1599        // NP-1+S
#define KPATCH_   588         // 3*14*14
#define M_        (B_*NP_)    // 4608 rows of image features
#define IMAGE_TOKEN_ 32000

// output layout (float32, tuple flattened in order)
#define OFF_EMB   1LL
#define N_EMB     ((long long)B_*MAXE_*D_)          // 52,396,032
#define OFF_ATTN  (OFF_EMB + N_EMB)
#define OFF_LAB   (OFF_ATTN + (long long)B_*MAXE_)
#define OFF_ROUT  (OFF_LAB  + (long long)B_*MAXE_)
#define N_TAIL    (32LL*MAXE_*8 + 32LL*MAXE_*2)     // 511,680 zeros

// ---------------- device scratch ----------------
__device__ float g_h[M_ * DV_];   // patch-embed output  (18.9 MB)
__device__ float g_g[M_ * D_];    // gelu(h@w1+b1)       (75.5 MB)
__device__ int   g_spos[B_];

__device__ __forceinline__ float gelu_tanh(float x) {
    float x3 = x * x * x;
    return 0.5f * x * (1.0f + tanhf(0.7978845608028654f * (x + 0.044715f * x3)));
}

// ---------------- small kernels ----------------
__global__ void k_fill(float* __restrict__ out) {
    long long i = (long long)blockIdx.x * blockDim.x + threadIdx.x;
    if (i == 0) out[0] = 0.0f;                 // current_layer
    if (i < B_) g_spos[i] = S_;
    long long stride = (long long)gridDim.x * blockDim.x;
    for (long long j = i; j < N_TAIL; j += stride)
        out[OFF_ROUT + j] = 0.0f;              // router + shared logits
}

__global__ void k_spos(const int* __restrict__ ids) {
    int i = blockIdx.x * blockDim.x + threadIdx.x;
    if (i < B_ * S_ && ids[i] == IMAGE_TOKEN_)
        atomicMin(&g_spos[i / S_], i % S_);
}

// one block per (b, s): copy embed row + attn + label to merged position
__global__ void k_text(const int* __restrict__ ids, const int* __restrict__ mask,
                       const int* __restrict__ labels, const float* __restrict__ table,
                       float* __restrict__ out) {
    int bs = blockIdx.x;                 // 0..B*S-1
    int b = bs / S_, s = bs - b * S_;
    int id = ids[bs];
    if (id == IMAGE_TOKEN_) return;      // special token is dropped
    int sp = g_spos[b];
    int dest = s + (s > sp ? (NP_ - 1) : 0);
    const float* __restrict__ src = table + (long long)id * D_;
    float* __restrict__ dst = out + OFF_EMB + ((long long)b * MAXE_ + dest) * D_;
    for (int j = threadIdx.x; j < D_; j += blockDim.x)
        dst[j] = src[j];
    if (threadIdx.x == 0) {
        out[OFF_ATTN + (long long)b * MAXE_ + dest] = (float)mask[bs];
        out[OFF_LAB  + (long long)b * MAXE_ + dest] = (float)labels[bs];
    }
}

__global__ void k_imgmeta(float* __restrict__ out) {
    int i = blockIdx.x * blockDim.x + threadIdx.x;
    if (i >= B_ * NP_) return;
    int b = i / NP_, t = i - b * NP_;
    int dest = g_spos[b] + t;
    out[OFF_ATTN + (long long)b * MAXE_ + dest] = 1.0f;
    out[OFF_LAB  + (long long)b * MAXE_ + dest] = -100.0f;
}

// ---------------- patch-embed GEMM: h = gather(pixels) @ patch_w + patch_b ----------------
// M=4608, N=1024, K=588.  A is gathered on the fly from pixel_values.
__global__ void __launch_bounds__(256)
k_patch(const float* __restrict__ pix, const float* __restrict__ Bw,
        const float* __restrict__ bias) {
    __shared__ float As[16][132];
    __shared__ float Bs[16][132];
    int t  = threadIdx.x;
    int m0 = blockIdx.y * 128;
    int n0 = blockIdx.x * 128;
    float acc[8][8] = {};
    int brow = t >> 5, bcol = t & 31;
    int rm = (t >> 4) * 8, rn = (t & 15) * 8;

    for (int k0 = 0; k0 < KPATCH_; k0 += 16) {
        // gather A tile (2048 elems, 8 per thread)
        #pragma unroll
        for (int i = 0; i < 8; i++) {
            int idx = t + 256 * i;
            int r  = idx >> 4;          // 0..127
            int kk = idx & 15;
            int k  = k0 + kk;
            float v = 0.0f;
            if (k < KPATCH_) {
                int m  = m0 + r;
                int ni = m / NP_;
                int tt = m - ni * NP_;
                int gi = tt / GRID_, gj = tt - gi * GRID_;
                int c  = k / 196;
                int rem = k - c * 196;
                int pi = rem / PATCH_, pj = rem - pi * PATCH_;
                long long addr = (((long long)ni * 3 + c) * IMG_ + gi * PATCH_ + pi) * IMG_
                               + gj * PATCH_ + pj;
                v = pix[addr];
            }
            As[kk][r] = v;
        }
        // B tile (patch_w is K x N row-major), guard k
        #pragma unroll
        for (int i = 0; i < 2; i++) {
            int kk = brow + i * 8;
            int k  = k0 + kk;
            float4 v = make_float4(0.f, 0.f, 0.f, 0.f);
            if (k < KPATCH_)
                v = *(const float4*)(Bw + (long long)k * DV_ + n0 + bcol * 4);
            *(float4*)(&Bs[kk][bcol * 4]) = v;
        }
        __syncthreads();
        #pragma unroll
        for (int k = 0; k < 16; k++) {
            float ra[8], rb[8];
            #pragma unroll
            for (int i = 0; i < 8; i++) ra[i] = As[k][rm + i];
            #pragma unroll
            for (int j = 0; j < 8; j++) rb[j] = Bs[k][rn + j];
            #pragma unroll
            for (int i = 0; i < 8; i++)
                #pragma unroll
                for (int j = 0; j < 8; j++)
                    acc[i][j] += ra[i] * rb[j];
        }
        __syncthreads();
    }
    #pragma unroll
    for (int i = 0; i < 8; i++) {
        int m = m0 + rm + i;
        #pragma unroll
        for (int j = 0; j < 8; j++) {
            int n = n0 + rn + j;
            g_h[(long long)m * DV_ + n] = acc[i][j] + bias[n];
        }
    }
}

// ---------------- generic 128x128x16 SGEMM ----------------
// EPI==1: A=g_h (K=1024), C = gelu(A@B + bias) -> g_g
// EPI==2: A=g_g (K=4096), scatter A@B + bias into final_emb image rows
template<int EPI>
__global__ void __launch_bounds__(256)
k_sgemm(const float* __restrict__ Bw, const float* __restrict__ bias,
        float* __restrict__ out, int N, int K) {
    const float* __restrict__ A = (EPI == 1) ? g_h : g_g;
    __shared__ float As[16][132];
    __shared__ float Bs[16][132];
    int t  = threadIdx.x;
    int m0 = blockIdx.y * 128;
    int n0 = blockIdx.x * 128;
    float acc[8][8] = {};
    int arow = t >> 2, acol = t & 3;     // 512 float4 per A tile, 2 per thread
    int brow = t >> 5, bcol = t & 31;
    int rm = (t >> 4) * 8, rn = (t & 15) * 8;

    for (int k0 = 0; k0 < K; k0 += 16) {
        #pragma unroll
        for (int i = 0; i < 2; i++) {
            int r = arow + i * 64;
            float4 v = *(const float4*)(A + (long long)(m0 + r) * K + k0 + acol * 4);
            As[acol * 4 + 0][r] = v.x;
            As[acol * 4 + 1][r] = v.y;
            As[acol * 4 + 2][r] = v.z;
            As[acol * 4 + 3][r] = v.w;
        }
        #pragma unroll
        for (int i = 0; i < 2; i++) {
            int kk = brow + i * 8;
            *(float4*)(&Bs[kk][bcol * 4]) =
                *(const float4*)(Bw + (long long)(k0 + kk) * N + n0 + bcol * 4);
        }
        __syncthreads();
        #pragma unroll
        for (int k = 0; k < 16; k++) {
            float ra[8], rb[8];
            #pragma unroll
            for (int i = 0; i < 8; i++) ra[i] = As[k][rm + i];
            #pragma unroll
            for (int j = 0; j < 8; j++) rb[j] = Bs[k][rn + j];
            #pragma unroll
            for (int i = 0; i < 8; i++)
                #pragma unroll
                for (int j = 0; j < 8; j++)
                    acc[i][j] += ra[i] * rb[j];
        }
        __syncthreads();
    }

    #pragma unroll
    for (int i = 0; i < 8; i++) {
        int m = m0 + rm + i;
        long long rowbase = 0;
        if (EPI == 2) {
            int bb = m / NP_;
            int tt = m - bb * NP_;
            rowbase = OFF_EMB + ((long long)bb * MAXE_ + g_spos[bb] + tt) * (long long)D_;
        }
        #pragma unroll
        for (int j = 0; j < 8; j++) {
            int n = n0 + rn + j;
            float v = acc[i][j] + bias[n];
            if (EPI == 1) g_g[(long long)m * N + n] = gelu_tanh(v);
            else          out[rowbase + n] = v;
        }
    }
}

// ---------------- launch ----------------
extern "C" void kernel_launch(void* const* d_in, const int* in_sizes, int n_in,
                              void* d_out, int out_size) {
    const int*   ids     = (const int*)  d_in[0];
    const float* pix     = (const float*)d_in[1];
    const int*   mask    = (const int*)  d_in[2];
    const int*   labels  = (const int*)  d_in[3];
    const float* table   = (const float*)d_in[4];
    // d_in[5] = cls_emb, unused (sel = hidden[:,1:] drops the cls row)
    const float* patch_w = (const float*)d_in[6];
    const float* patch_b = (const float*)d_in[7];
    const float* w1      = (const float*)d_in[8];
    const float* b1      = (const float*)d_in[9];
    const float* w2      = (const float*)d_in[10];
    const float* b2      = (const float*)d_in[11];
    float* out = (float*)d_out;

    k_fill<<<512, 256>>>(out);
    k_spos<<<(B_ * S_ + 255) / 256, 256>>>(ids);
    k_text<<<B_ * S_, 256>>>(ids, mask, labels, table, out);
    k_imgmeta<<<(B_ * NP_ + 255) / 256, 256>>>(out);
    k_patch<<<dim3(DV_ / 128, M_ / 128), 256>>>(pix, patch_w, patch_b);
    k_sgemm<1><<<dim3(D_ / 128, M_ / 128), 256>>>(w1, b1, out, D_, DV_);
    k_sgemm<2><<<dim3(D_ / 128, M_ / 128), 256>>>(w2, b2, out, D_, D_);
}